// round 4
// baseline (speedup 1.0000x reference)
#include <cuda_runtime.h>

#define BB 64
#define VV 2000
#define FF 8
#define GG 80
#define NRR 5               // distinct mu_rho  (rows of polar grid)
#define NTT 16              // distinct mu_theta (cols of polar grid), g = r*16 + t
#define NROT 5
#define DD (FF*GG)          // 640
#define VCH 4               // vertex chunks per (b,k)
#define VCS (VV/VCH)        // 500
#define TPBA 256            // kernel A threads: 16 t-lanes x 16 v-slices
#define NSL 16
#define TPBB 512            // kernel B threads: 128 j-lanes x 4 i-segments
#define JT 5
#define BG 32
#define TWO_PI_F 6.283185307179586f
#define EPSF 1e-5f

// partial (unnormalized) sums: [bk][chunk][9][G]  (j=0: sum w; 1..8: sum w*feat)
__device__ float g_part[BB*NROT][VCH][9][GG];

// ---------------- packed f32x2 helpers ----------------
__device__ __forceinline__ unsigned long long pack2(float lo, float hi) {
    unsigned long long r;
    asm("mov.b64 %0, {%1, %2};" : "=l"(r) : "f"(lo), "f"(hi));
    return r;
}
__device__ __forceinline__ void fma2(unsigned long long& d,
                                     unsigned long long a, unsigned long long b) {
    asm("fma.rn.f32x2 %0, %1, %2, %3;" : "=l"(d) : "l"(a), "l"(b), "l"(d));
}
__device__ __forceinline__ void add2(unsigned long long& d, unsigned long long a) {
    asm("add.rn.f32x2 %0, %1, %2;" : "=l"(d) : "l"(d), "l"(a));
}
__device__ __forceinline__ float2 unpack2(unsigned long long v) {
    float lo, hi;
    asm("mov.b64 {%0, %1}, %2;" : "=f"(lo), "=f"(hi) : "l"(v));
    return make_float2(lo, hi);
}

// ---------------------------------------------------------------------------
// Kernel A: separable gaussian accumulation.
//   w[v, r*16+t] = Rm[v,r] * T[v,t]   (Rm includes mask)
// Each thread owns one t, loops r=0..4 with 5x(1 mul + 1 add + 4 FFMA2).
// ---------------------------------------------------------------------------
__global__ void __launch_bounds__(TPBA)
gauss_desc_kernel(const float* __restrict__ feat,
                  const float* __restrict__ rho,
                  const float* __restrict__ theta,
                  const float* __restrict__ mask,
                  const float* __restrict__ mu_rho,
                  const float* __restrict__ sigma_rho,
                  const float* __restrict__ mu_theta,
                  const float* __restrict__ sigma_theta)
{
    extern __shared__ float sm[];
    float* s_T    = sm;               // [VCS*16]   32000 B
    float* s_Rm   = sm + VCS*NTT;     // [VCS*8]    16000 B (stride 8, r<5 used)
    float* s_feat = sm + VCS*24;      // [VCS*8]    16000 B

    const int bk  = blockIdx.x;
    const int b   = bk / NROT;
    const int k   = bk % NROT;
    const int cv0 = blockIdx.y * VCS;
    const int tid = threadIdx.x;
    const float kdelta = (float)k * (TWO_PI_F / (float)NROT);

    // theta gaussians: 500 x 16
    for (int i = tid; i < VCS*NTT; i += TPBA) {
        int v = i >> 4, t = i & 15;
        float th = theta[b*VV + cv0 + v] + kdelta;
        if (th >= TWO_PI_F) th -= TWO_PI_F;        // theta in [0,2pi)
        float mut = mu_theta[t];
        float st  = sigma_theta[t];
        float d   = th - mut;
        s_T[i] = __expf(-d*d / (st*st + EPSF));
    }
    // rho gaussians * mask: 500 x 5
    for (int i = tid; i < VCS*NRR; i += TPBA) {
        int v = i / NRR, r = i - v*NRR;
        float rr  = rho[b*VV + cv0 + v];
        float mur = mu_rho[r*NTT];                 // grid: constant across t
        float sr  = sigma_rho[r*NTT];
        float d   = rr - mur;
        s_Rm[v*8 + r] = __expf(-d*d / (sr*sr + EPSF)) * mask[b*VV + cv0 + v];
    }
    for (int i = tid; i < VCS*FF; i += TPBA)
        s_feat[i] = feat[(b*VV + cv0)*FF + i];
    __syncthreads();

    const int t     = tid & 15;
    const int slice = tid >> 4;

    float a0[NRR] = {0.f, 0.f, 0.f, 0.f, 0.f};
    unsigned long long acc[NRR][4];
    #pragma unroll
    for (int r = 0; r < NRR; r++)
        #pragma unroll
        for (int a = 0; a < 4; a++) acc[r][a] = 0ull;

    for (int v = slice; v < VCS; v += NSL) {
        float tv = s_T[v*NTT + t];
        float4 rm4 = *(const float4*)(s_Rm + v*8);
        float  rm5 = s_Rm[v*8 + 4];
        ulonglong2 q0 = *(const ulonglong2*)(s_feat + v*8);
        ulonglong2 q1 = *(const ulonglong2*)(s_feat + v*8 + 4);
        float w; unsigned long long w2;
        w = rm4.x * tv; a0[0] += w; w2 = pack2(w, w);
        fma2(acc[0][0], w2, q0.x); fma2(acc[0][1], w2, q0.y);
        fma2(acc[0][2], w2, q1.x); fma2(acc[0][3], w2, q1.y);
        w = rm4.y * tv; a0[1] += w; w2 = pack2(w, w);
        fma2(acc[1][0], w2, q0.x); fma2(acc[1][1], w2, q0.y);
        fma2(acc[1][2], w2, q1.x); fma2(acc[1][3], w2, q1.y);
        w = rm4.z * tv; a0[2] += w; w2 = pack2(w, w);
        fma2(acc[2][0], w2, q0.x); fma2(acc[2][1], w2, q0.y);
        fma2(acc[2][2], w2, q1.x); fma2(acc[2][3], w2, q1.y);
        w = rm4.w * tv; a0[3] += w; w2 = pack2(w, w);
        fma2(acc[3][0], w2, q0.x); fma2(acc[3][1], w2, q0.y);
        fma2(acc[3][2], w2, q1.x); fma2(acc[3][3], w2, q1.y);
        w = rm5   * tv; a0[4] += w; w2 = pack2(w, w);
        fma2(acc[4][0], w2, q0.x); fma2(acc[4][1], w2, q0.y);
        fma2(acc[4][2], w2, q1.x); fma2(acc[4][3], w2, q1.y);
    }
    __syncthreads();           // T/Rm no longer needed; overlay reduction

    float* red = sm;           // [256][45] = 46080 B (< 64000)
    {
        const int base = tid * 45;
        #pragma unroll
        for (int r = 0; r < NRR; r++) {
            red[base + r*9] = a0[r];
            #pragma unroll
            for (int a = 0; a < 4; a++) {
                float2 u = unpack2(acc[r][a]);
                red[base + r*9 + 1 + 2*a] = u.x;
                red[base + r*9 + 2 + 2*a] = u.y;
            }
        }
    }
    __syncthreads();

    for (int e = tid; e < 9*GG; e += TPBA) {
        int j = e / GG, g = e - (e / GG)*GG;
        int r = g >> 4, tt = g & 15;
        float S = 0.f;
        #pragma unroll
        for (int s = 0; s < NSL; s++)
            S += red[((s << 4) | tt)*45 + r*9 + j];
        g_part[bk][blockIdx.y][j][g] = S;
    }
}

// ---------------------------------------------------------------------------
// Kernel B: normalize, then out[b,j] = relu(max_k desc_k@W[:,j] + bias[j]).
// 512 threads = 128 j-lanes x 4 i-segments; 10 packed accs each; packed
// smem combine over segments.
// ---------------------------------------------------------------------------
__global__ void __launch_bounds__(TPBB)
gemm_max_relu_kernel(const float* __restrict__ Wm,
                     const float* __restrict__ bias,
                     float* __restrict__ out)
{
    __shared__ __align__(16) char smB[TPBB*10*8];      // 40960 B (union)
    float* s_desc = (float*)smB;                        // [2][5][640] = 25600 B
    unsigned long long* red = (unsigned long long*)smB; // [512][10]

    const int tid = threadIdx.x;
    const int b0  = blockIdx.y * 2;

    // chunk-sum + normalize descriptors for 2 b's x 5 rotations
    for (int e = tid; e < 2*NROT*GG; e += TPBB) {
        int bb = e / (NROT*GG);
        int r  = e - bb*(NROT*GG);
        int kk = r / GG;
        int g  = r - kk*GG;
        int bk = (b0 + bb)*NROT + kk;
        float S[9];
        #pragma unroll
        for (int j = 0; j < 9; j++) S[j] = 0.0f;
        #pragma unroll
        for (int c = 0; c < VCH; c++)
            #pragma unroll
            for (int j = 0; j < 9; j++) S[j] += g_part[bk][c][j][g];
        float inv = 1.0f / (S[0] + EPSF);
        #pragma unroll
        for (int f = 0; f < FF; f++)
            s_desc[(bb*NROT + kk)*DD + f*GG + g] = S[1 + f] * inv;
    }
    __syncthreads();

    const int tx  = tid & 127;
    const int seg = tid >> 7;
    const int j   = blockIdx.x * 128 + tx;
    const int i0  = seg * (DD/4);                 // 160-row segment

    unsigned long long acc[10];
    #pragma unroll
    for (int a = 0; a < 10; a++) acc[a] = 0ull;

    #pragma unroll 2
    for (int i = i0; i < i0 + DD/4; i += 4) {
        float w0 = Wm[(i+0)*DD + j];
        float w1 = Wm[(i+1)*DD + j];
        float w2 = Wm[(i+2)*DD + j];
        float w3 = Wm[(i+3)*DD + j];
        unsigned long long wp0 = pack2(w0, w1);
        unsigned long long wp1 = pack2(w2, w3);
        #pragma unroll
        for (int a = 0; a < 10; a++) {
            ulonglong2 d = *(const ulonglong2*)&s_desc[a*DD + i];
            fma2(acc[a], d.x, wp0);
            fma2(acc[a], d.y, wp1);
        }
    }
    __syncthreads();                               // everyone done reading desc

    #pragma unroll
    for (int a = 0; a < 10; a++) red[tid*10 + a] = acc[a];
    __syncthreads();

    if (tid < 128) {
        const float bj = bias[j];
        #pragma unroll
        for (int bb = 0; bb < 2; bb++) {
            float m = -3.4e38f;
            #pragma unroll
            for (int kk = 0; kk < NROT; kk++) {
                int a = bb*NROT + kk;
                unsigned long long s = red[tid*10 + a];
                add2(s, red[(128 + tid)*10 + a]);
                add2(s, red[(256 + tid)*10 + a]);
                add2(s, red[(384 + tid)*10 + a]);
                float2 u = unpack2(s);
                m = fmaxf(m, u.x + u.y);
            }
            out[(b0 + bb)*DD + j] = fmaxf(m + bj, 0.0f);
        }
    }
}

// ---------------------------------------------------------------------------

extern "C" void kernel_launch(void* const* d_in, const int* in_sizes, int n_in,
                              void* d_out, int out_size) {
    const float* feat        = (const float*)d_in[0];
    const float* rho         = (const float*)d_in[1];
    const float* theta       = (const float*)d_in[2];
    const float* mask        = (const float*)d_in[3];
    const float* mu_rho      = (const float*)d_in[4];
    const float* sigma_rho   = (const float*)d_in[5];
    const float* mu_theta    = (const float*)d_in[6];
    const float* sigma_theta = (const float*)d_in[7];
    const float* Wm          = (const float*)d_in[8];
    const float* bias        = (const float*)d_in[9];
    float* out = (float*)d_out;

    const int smemA = VCS * 32 * sizeof(float);    // 64000 B
    static int attr_set = 0;
    cudaFuncSetAttribute(gauss_desc_kernel,
                         cudaFuncAttributeMaxDynamicSharedMemorySize, smemA);
    (void)attr_set;

    gauss_desc_kernel<<<dim3(BB*NROT, VCH), TPBA, smemA>>>(
        feat, rho, theta, mask, mu_rho, sigma_rho, mu_theta, sigma_theta);

    gemm_max_relu_kernel<<<dim3(JT, BG), TPBB>>>(Wm, bias, out);
}

// round 5
// speedup vs baseline: 1.3159x; 1.3159x over previous
#include <cuda_runtime.h>

#define BB 64
#define VV 2000
#define FF 8
#define GG 80
#define NRR 5               // distinct mu_rho  (g = r*16 + t)
#define NTT 16              // distinct mu_theta
#define NROT 5
#define DD (FF*GG)          // 640
#define VCH 4               // vertex chunks per (b,k)
#define VCS (VV/VCH)        // 500
#define NSLICE 4
#define TPB (GG*NSLICE)     // 320 threads kernel A
#define TPBB 512            // kernel B: 128 j-lanes x 4 i-segments
#define JT 5
#define BG 32
#define TWO_PI_F 6.283185307179586f
#define EPSF 1e-5f

// partial (unnormalized) sums: [bk][chunk][9][G]  (0: sum w; 1..8: sum w*feat)
__device__ float g_part[BB*NROT][VCH][9][GG];

// ---------------- packed f32x2 helpers ----------------
__device__ __forceinline__ unsigned long long pack2(float lo, float hi) {
    unsigned long long r;
    asm("mov.b64 %0, {%1, %2};" : "=l"(r) : "f"(lo), "f"(hi));
    return r;
}
__device__ __forceinline__ void fma2(unsigned long long& d,
                                     unsigned long long a, unsigned long long b) {
    asm("fma.rn.f32x2 %0, %1, %2, %3;" : "=l"(d) : "l"(a), "l"(b), "l"(d));
}
__device__ __forceinline__ void add2(unsigned long long& d, unsigned long long a) {
    asm("add.rn.f32x2 %0, %1, %2;" : "=l"(d) : "l"(d), "l"(a));
}
__device__ __forceinline__ float2 unpack2(unsigned long long v) {
    float lo, hi;
    asm("mov.b64 {%0, %1}, %2;" : "=f"(lo), "=f"(hi) : "l"(v));
    return make_float2(lo, hi);
}

// ---------------------------------------------------------------------------
// Kernel A: separable gaussians, thread-per-gaussian mapping (proven layout).
//   w[v, r*16+t] = Rm[v,r] * T[v,t]   (Rm includes mask)
// Only 21 exps per vertex (staging), then inner loop is
// 2 LDS + FMUL + FADD + 4 FFMA2 per (v,g). 5 accumulator chains per thread.
// ---------------------------------------------------------------------------
__global__ void __launch_bounds__(TPB)
gauss_desc_kernel(const float* __restrict__ feat,
                  const float* __restrict__ rho,
                  const float* __restrict__ theta,
                  const float* __restrict__ mask,
                  const float* __restrict__ mu_rho,
                  const float* __restrict__ sigma_rho,
                  const float* __restrict__ mu_theta,
                  const float* __restrict__ sigma_theta)
{
    extern __shared__ float sm[];
    float* s_T    = sm;               // [VCS*16]  32000 B
    float* s_Rm   = sm + VCS*NTT;     // [VCS*8]   16000 B (stride 8, r<5 used)
    float* s_feat = sm + VCS*24;      // [VCS*8]   16000 B

    const int bk  = blockIdx.x;
    const int b   = bk / NROT;
    const int k   = bk % NROT;
    const int cv0 = blockIdx.y * VCS;
    const int tid = threadIdx.x;
    const float kdelta = (float)k * (TWO_PI_F / (float)NROT);

    // theta gaussians: 500 x 16
    for (int i = tid; i < VCS*NTT; i += TPB) {
        int v = i >> 4, t = i & 15;
        float th = theta[b*VV + cv0 + v] + kdelta;
        if (th >= TWO_PI_F) th -= TWO_PI_F;          // theta in [0,2pi)
        float st = sigma_theta[t];
        float d  = th - mu_theta[t];
        s_T[i] = __expf(-d*d / (st*st + EPSF));
    }
    // rho gaussians * mask: 500 x 5
    for (int i = tid; i < VCS*NRR; i += TPB) {
        int v = i / NRR, r = i - v*NRR;
        float sr = sigma_rho[r*NTT];                 // grid: constant across t
        float d  = rho[b*VV + cv0 + v] - mu_rho[r*NTT];
        s_Rm[v*8 + r] = __expf(-d*d / (sr*sr + EPSF)) * mask[b*VV + cv0 + v];
    }
    for (int i = tid; i < VCS*FF/4; i += TPB)
        ((float4*)s_feat)[i] = ((const float4*)(feat + (size_t)(b*VV + cv0)*FF))[i];
    __syncthreads();

    const int g     = tid % GG;
    const int slice = tid / GG;
    const int r     = g >> 4;
    const int t     = g & 15;

    float a0 = 0.0f;
    unsigned long long acc[4] = {0ull, 0ull, 0ull, 0ull};

    for (int v = slice; v < VCS; v += NSLICE) {
        float tv = s_T[v*NTT + t];
        float rv = s_Rm[v*8 + r];
        float w  = rv * tv;
        a0 += w;
        unsigned long long w2 = pack2(w, w);
        ulonglong2 q0 = *(const ulonglong2*)(s_feat + v*FF);
        ulonglong2 q1 = *(const ulonglong2*)(s_feat + v*FF + 4);
        fma2(acc[0], w2, q0.x);
        fma2(acc[1], w2, q0.y);
        fma2(acc[2], w2, q1.x);
        fma2(acc[3], w2, q1.y);
    }
    __syncthreads();           // vertex data dead; overlay reduction

    float* red = sm;           // [9][TPB] = 11520 B
    red[0*TPB + tid] = a0;
    #pragma unroll
    for (int a = 0; a < 4; a++) {
        float2 u = unpack2(acc[a]);
        red[(1 + 2*a)*TPB + tid] = u.x;
        red[(2 + 2*a)*TPB + tid] = u.y;
    }
    __syncthreads();

    for (int e = tid; e < 9*GG; e += TPB) {
        int j  = e / GG;
        int gg = e - j*GG;
        float S = red[j*TPB + gg] + red[j*TPB + GG + gg]
                + red[j*TPB + 2*GG + gg] + red[j*TPB + 3*GG + gg];
        g_part[bk][blockIdx.y][j][gg] = S;
    }
}

// ---------------------------------------------------------------------------
// Kernel B: normalize, then out[b,j] = relu(max_k desc_k@W[:,j] + bias[j]).
// 512 threads = 128 j-lanes x 4 i-segments; 10 packed accs each; unroll 8
// for deep LDG pipelining; packed smem combine over segments.
// ---------------------------------------------------------------------------
__global__ void __launch_bounds__(TPBB)
gemm_max_relu_kernel(const float* __restrict__ Wm,
                     const float* __restrict__ bias,
                     float* __restrict__ out)
{
    __shared__ __align__(16) char smB[TPBB*10*8];      // 40960 B (union)
    float* s_desc = (float*)smB;                        // [2][5][640] = 25600 B
    unsigned long long* red = (unsigned long long*)smB; // [512][10]

    const int tid = threadIdx.x;
    const int b0  = blockIdx.y * 2;

    // chunk-sum + normalize descriptors for 2 b's x 5 rotations
    for (int e = tid; e < 2*NROT*GG; e += TPBB) {
        int bb = e / (NROT*GG);
        int rr = e - bb*(NROT*GG);
        int kk = rr / GG;
        int g  = rr - kk*GG;
        int bk = (b0 + bb)*NROT + kk;
        float S[9];
        #pragma unroll
        for (int j = 0; j < 9; j++) S[j] = 0.0f;
        #pragma unroll
        for (int c = 0; c < VCH; c++)
            #pragma unroll
            for (int j = 0; j < 9; j++) S[j] += g_part[bk][c][j][g];
        float inv = 1.0f / (S[0] + EPSF);
        #pragma unroll
        for (int f = 0; f < FF; f++)
            s_desc[(bb*NROT + kk)*DD + f*GG + g] = S[1 + f] * inv;
    }
    __syncthreads();

    const int tx  = tid & 127;
    const int seg = tid >> 7;
    const int j   = blockIdx.x * 128 + tx;
    const int i0  = seg * (DD/4);                 // 160-row segment

    unsigned long long acc[10];
    #pragma unroll
    for (int a = 0; a < 10; a++) acc[a] = 0ull;

    #pragma unroll 8
    for (int i = i0; i < i0 + DD/4; i += 4) {
        float w0 = Wm[(i+0)*DD + j];
        float w1 = Wm[(i+1)*DD + j];
        float w2 = Wm[(i+2)*DD + j];
        float w3 = Wm[(i+3)*DD + j];
        unsigned long long wp0 = pack2(w0, w1);
        unsigned long long wp1 = pack2(w2, w3);
        #pragma unroll
        for (int a = 0; a < 10; a++) {
            ulonglong2 d = *(const ulonglong2*)&s_desc[a*DD + i];
            fma2(acc[a], d.x, wp0);
            fma2(acc[a], d.y, wp1);
        }
    }
    __syncthreads();                               // everyone done reading desc

    #pragma unroll
    for (int a = 0; a < 10; a++) red[tid*10 + a] = acc[a];
    __syncthreads();

    if (tid < 128) {
        const float bj = bias[j];
        #pragma unroll
        for (int bb = 0; bb < 2; bb++) {
            float m = -3.4e38f;
            #pragma unroll
            for (int kk = 0; kk < NROT; kk++) {
                int a = bb*NROT + kk;
                unsigned long long s = red[tid*10 + a];
                add2(s, red[(128 + tid)*10 + a]);
                add2(s, red[(256 + tid)*10 + a]);
                add2(s, red[(384 + tid)*10 + a]);
                float2 u = unpack2(s);
                m = fmaxf(m, u.x + u.y);
            }
            out[(b0 + bb)*DD + j] = fmaxf(m + bj, 0.0f);
        }
    }
}

// ---------------------------------------------------------------------------

extern "C" void kernel_launch(void* const* d_in, const int* in_sizes, int n_in,
                              void* d_out, int out_size) {
    const float* feat        = (const float*)d_in[0];
    const float* rho         = (const float*)d_in[1];
    const float* theta       = (const float*)d_in[2];
    const float* mask        = (const float*)d_in[3];
    const float* mu_rho      = (const float*)d_in[4];
    const float* sigma_rho   = (const float*)d_in[5];
    const float* mu_theta    = (const float*)d_in[6];
    const float* sigma_theta = (const float*)d_in[7];
    const float* Wm          = (const float*)d_in[8];
    const float* bias        = (const float*)d_in[9];
    float* out = (float*)d_out;

    const int smemA = VCS * 32 * sizeof(float);    // 64000 B
    cudaFuncSetAttribute(gauss_desc_kernel,
                         cudaFuncAttributeMaxDynamicSharedMemorySize, smemA);

    gauss_desc_kernel<<<dim3(BB*NROT, VCH), TPB, smemA>>>(
        feat, rho, theta, mask, mu_rho, sigma_rho, mu_theta, sigma_theta);

    gemm_max_relu_kernel<<<dim3(JT, BG), TPBB>>>(Wm, bias, out);
}

// round 6
// speedup vs baseline: 1.6413x; 1.2473x over previous
#include <cuda_runtime.h>

#define BB 64
#define VV 2000
#define FF 8
#define GG 80
#define NROT 5
#define DD (FF*GG)          // 640
#define VCH 4               // vertex chunks per (b,k)
#define VCS (VV/VCH)        // 500
#define NSLICE 4
#define TPB (GG*NSLICE)     // 320 threads kernel A
#define TPBB 256            // kernel B: 64 j-lanes x 4 i-segments
#define JT 10               // j tiles of 64
#define BG 32               // b groups of 2
#define TWO_PI_F 6.283185307179586f
#define EPSF 1e-5f

// partial (unnormalized) sums: [bk][chunk][9][G]  (0: sum w; 1..8: sum w*feat)
__device__ float g_part[BB*NROT][VCH][9][GG];

// ---------------- packed f32x2 helpers ----------------
__device__ __forceinline__ unsigned long long pack2(float lo, float hi) {
    unsigned long long r;
    asm("mov.b64 %0, {%1, %2};" : "=l"(r) : "f"(lo), "f"(hi));
    return r;
}
__device__ __forceinline__ void fma2(unsigned long long& d,
                                     unsigned long long a, unsigned long long b) {
    asm("fma.rn.f32x2 %0, %1, %2, %3;" : "=l"(d) : "l"(a), "l"(b), "l"(d));
}
__device__ __forceinline__ void add2(unsigned long long& d, unsigned long long a) {
    asm("add.rn.f32x2 %0, %1, %2;" : "=l"(d) : "l"(d), "l"(a));
}
__device__ __forceinline__ float2 unpack2(unsigned long long v) {
    float lo, hi;
    asm("mov.b64 {%0, %1}, %2;" : "=f"(lo), "=f"(hi) : "l"(v));
    return make_float2(lo, hi);
}

// ---------------------------------------------------------------------------
// Kernel A (proven 26.7us form): per (b,k,chunk) accumulate gaussian sums.
//   w = exp(c0 + c1*rho - isr*rho^2 + c2*th - ist*th^2) * mask
// Reciprocals hoisted per-thread; 5 accumulator chains (1 scalar + 4 f32x2).
// ---------------------------------------------------------------------------
__global__ void __launch_bounds__(TPB)
gauss_desc_kernel(const float* __restrict__ feat,
                  const float* __restrict__ rho,
                  const float* __restrict__ theta,
                  const float* __restrict__ mask,
                  const float* __restrict__ mu_rho,
                  const float* __restrict__ sigma_rho,
                  const float* __restrict__ mu_theta,
                  const float* __restrict__ sigma_theta)
{
    __shared__ float4 s_pack[VCS];                    // {rho, rho^2, th, th^2}
    __shared__ float  s_mask[VCS];
    __shared__ __align__(16) float s_feat[VCS*FF];
    __shared__ float  red[9][TPB];

    const int bk  = blockIdx.x;
    const int b   = bk / NROT;
    const int k   = bk % NROT;
    const int cv0 = blockIdx.y * VCS;
    const int tid = threadIdx.x;
    const float kdelta = (float)k * (TWO_PI_F / (float)NROT);

    for (int v = tid; v < VCS; v += TPB) {
        float r = rho[b*VV + cv0 + v];
        float t = theta[b*VV + cv0 + v] + kdelta;
        if (t >= TWO_PI_F) t -= TWO_PI_F;             // theta in [0,2pi)
        s_pack[v] = make_float4(r, r*r, t, t*t);
        s_mask[v] = mask[b*VV + cv0 + v];
    }
    for (int i = tid; i < VCS*FF/4; i += TPB)
        ((float4*)s_feat)[i] = ((const float4*)(feat + (size_t)(b*VV + cv0)*FF))[i];
    __syncthreads();

    const int g = tid % GG;
    const int s = tid / GG;

    const float mur = mu_rho[g];
    const float mut = mu_theta[g];
    const float sr  = sigma_rho[g];
    const float st  = sigma_theta[g];
    const float isr = 1.0f / (sr*sr + EPSF);
    const float ist = 1.0f / (st*st + EPSF);
    const float c1  = 2.0f * mur * isr;
    const float c2  = 2.0f * mut * ist;
    const float c0  = -(mur*mur*isr + mut*mut*ist);

    float a0 = 0.0f;
    unsigned long long acc[4] = {0ull, 0ull, 0ull, 0ull};

    for (int v = s; v < VCS; v += NSLICE) {
        float4 p = s_pack[v];
        float arg = fmaf(c1,  p.x, c0);
        arg       = fmaf(-isr, p.y, arg);
        arg       = fmaf(c2,  p.z, arg);
        arg       = fmaf(-ist, p.w, arg);
        float w = __expf(arg) * s_mask[v];
        a0 += w;
        unsigned long long w2 = pack2(w, w);
        const ulonglong2* fp = (const ulonglong2*)(s_feat + v*FF);
        ulonglong2 q0 = fp[0];
        ulonglong2 q1 = fp[1];
        fma2(acc[0], w2, q0.x);
        fma2(acc[1], w2, q0.y);
        fma2(acc[2], w2, q1.x);
        fma2(acc[3], w2, q1.y);
    }

    red[0][tid] = a0;
    #pragma unroll
    for (int a = 0; a < 4; a++) {
        float2 u = unpack2(acc[a]);
        red[1 + 2*a][tid] = u.x;
        red[2 + 2*a][tid] = u.y;
    }
    __syncthreads();

    for (int e = tid; e < 9*GG; e += TPB) {
        int j  = e / GG;
        int gg = e % GG;
        float S = red[j][gg] + red[j][GG + gg] + red[j][2*GG + gg] + red[j][3*GG + gg];
        g_part[bk][blockIdx.y][j][gg] = S;
    }
}

// ---------------------------------------------------------------------------
// Kernel B: normalize, then out[b,j] = relu(max_k desc_k@W[:,j] + bias[j]).
// 320 blocks x 256 threads = (64 j-lanes x 4 i-segments) x (10 j-tiles x 32
// b-pairs). 10 packed accs per thread; unroll 8; packed smem segment combine.
// ---------------------------------------------------------------------------
__global__ void __launch_bounds__(TPBB)
gemm_max_relu_kernel(const float* __restrict__ Wm,
                     const float* __restrict__ bias,
                     float* __restrict__ out)
{
    __shared__ __align__(16) char smB[2*NROT*DD*4];    // 25600 B (union)
    float* s_desc = (float*)smB;                        // [2][5][640]
    unsigned long long* red = (unsigned long long*)smB; // [256][10] = 20480 B

    const int tid = threadIdx.x;
    const int b0  = blockIdx.y * 2;

    // chunk-sum + normalize descriptors for 2 b's x 5 rotations
    for (int e = tid; e < 2*NROT*GG; e += TPBB) {
        int bb = e / (NROT*GG);
        int rr = e - bb*(NROT*GG);
        int kk = rr / GG;
        int g  = rr - kk*GG;
        int bk = (b0 + bb)*NROT + kk;
        float S[9];
        #pragma unroll
        for (int j = 0; j < 9; j++) S[j] = 0.0f;
        #pragma unroll
        for (int c = 0; c < VCH; c++)
            #pragma unroll
            for (int j = 0; j < 9; j++) S[j] += g_part[bk][c][j][g];
        float inv = 1.0f / (S[0] + EPSF);
        #pragma unroll
        for (int f = 0; f < FF; f++)
            s_desc[(bb*NROT + kk)*DD + f*GG + g] = S[1 + f] * inv;
    }
    __syncthreads();

    const int tx  = tid & 63;
    const int seg = tid >> 6;
    const int j   = blockIdx.x * 64 + tx;
    const int i0  = seg * (DD/4);                 // 160-row segment

    unsigned long long acc[10];
    #pragma unroll
    for (int a = 0; a < 10; a++) acc[a] = 0ull;

    #pragma unroll 8
    for (int i = i0; i < i0 + DD/4; i += 4) {
        float w0 = Wm[(i+0)*DD + j];
        float w1 = Wm[(i+1)*DD + j];
        float w2 = Wm[(i+2)*DD + j];
        float w3 = Wm[(i+3)*DD + j];
        unsigned long long wp0 = pack2(w0, w1);
        unsigned long long wp1 = pack2(w2, w3);
        #pragma unroll
        for (int a = 0; a < 10; a++) {
            ulonglong2 d = *(const ulonglong2*)&s_desc[a*DD + i];
            fma2(acc[a], d.x, wp0);
            fma2(acc[a], d.y, wp1);
        }
    }
    __syncthreads();                               // everyone done reading desc

    #pragma unroll
    for (int a = 0; a < 10; a++) red[tid*10 + a] = acc[a];
    __syncthreads();

    if (tid < 64) {
        const float bj = bias[j];
        #pragma unroll
        for (int bb = 0; bb < 2; bb++) {
            float m = -3.4e38f;
            #pragma unroll
            for (int kk = 0; kk < NROT; kk++) {
                int a = bb*NROT + kk;
                unsigned long long s = red[tid*10 + a];
                add2(s, red[(64  + tid)*10 + a]);
                add2(s, red[(128 + tid)*10 + a]);
                add2(s, red[(192 + tid)*10 + a]);
                float2 u = unpack2(s);
                m = fmaxf(m, u.x + u.y);
            }
            out[(b0 + bb)*DD + j] = fmaxf(m + bj, 0.0f);
        }
    }
}

// ---------------------------------------------------------------------------

extern "C" void kernel_launch(void* const* d_in, const int* in_sizes, int n_in,
                              void* d_out, int out_size) {
    const float* feat        = (const float*)d_in[0];
    const float* rho         = (const float*)d_in[1];
    const float* theta       = (const float*)d_in[2];
    const float* mask        = (const float*)d_in[3];
    const float* mu_rho      = (const float*)d_in[4];
    const float* sigma_rho   = (const float*)d_in[5];
    const float* mu_theta    = (const float*)d_in[6];
    const float* sigma_theta = (const float*)d_in[7];
    const float* Wm          = (const float*)d_in[8];
    const float* bias        = (const float*)d_in[9];
    float* out = (float*)d_out;

    gauss_desc_kernel<<<dim3(BB*NROT, VCH), TPB>>>(
        feat, rho, theta, mask, mu_rho, sigma_rho, mu_theta, sigma_theta);

    gemm_max_relu_kernel<<<dim3(JT, BG), TPBB>>>(Wm, bias, out);
}